// round 1
// baseline (speedup 1.0000x reference)
#include <cuda_runtime.h>
#include <cuda_bf16.h>

#define N_NODES 50000
#define D 128
#define N_EDGES 640000

// Scratch: aggregated neighbor sums (25.6 MB). Device global — no allocs allowed.
__device__ float g_agg[(size_t)N_NODES * D];
// Index dtype flag: 1 if src/dst are int64, 0 if int32. Set per-launch by detect_kernel.
__device__ int g_is64;

// ---------------------------------------------------------------------------
// Detect whether the edge index arrays are int64 or int32.
// If the data is int32, reading it as int64 packs two indices per word; the
// high half is a node index (nonzero with prob ~1-2e-5), so any of the 128
// checked values being outside [0, N_NODES) identifies int32.
// ---------------------------------------------------------------------------
__global__ void detect_kernel(const void* __restrict__ srcp,
                              const void* __restrict__ dstp) {
    if (threadIdx.x == 0 && blockIdx.x == 0) {
        const long long* s64 = (const long long*)srcp;
        const long long* d64 = (const long long*)dstp;
        int ok = 1;
        for (int i = 0; i < 64; i++) {
            long long a = s64[i];
            long long b = d64[i];
            if (a < 0 || a >= N_NODES || b < 0 || b >= N_NODES) { ok = 0; break; }
        }
        g_is64 = ok;
    }
}

// ---------------------------------------------------------------------------
// Zero the aggregation scratch (float4 stores, grid-stride).
// ---------------------------------------------------------------------------
__global__ void zero_kernel() {
    float4* p = (float4*)g_agg;
    const int n = N_NODES * D / 4;
    for (int i = blockIdx.x * blockDim.x + threadIdx.x; i < n;
         i += gridDim.x * blockDim.x) {
        p[i] = make_float4(0.f, 0.f, 0.f, 0.f);
    }
}

// ---------------------------------------------------------------------------
// Edge aggregation: one warp per edge. Lane l handles floats [4l, 4l+4) of the
// 128-wide row. Gather is a coalesced 512B row read (features table is fully
// L2-resident); scatter is atomicAdd (emitted as REDG, no return value).
// ---------------------------------------------------------------------------
__global__ void edge_kernel(const float* __restrict__ feat,
                            const void* __restrict__ srcp,
                            const void* __restrict__ dstp) {
    int w = (blockIdx.x * blockDim.x + threadIdx.x) >> 5;
    int lane = threadIdx.x & 31;
    if (w >= N_EDGES) return;

    long long s, d;
    if (g_is64) {
        s = ((const long long*)srcp)[w];
        d = ((const long long*)dstp)[w];
    } else {
        s = (long long)((const int*)srcp)[w];
        d = (long long)((const int*)dstp)[w];
    }

    float4 v = ((const float4*)(feat + (size_t)s * D))[lane];
    float* a = g_agg + (size_t)d * D + lane * 4;
    atomicAdd(a + 0, v.x);
    atomicAdd(a + 1, v.y);
    atomicAdd(a + 2, v.z);
    atomicAdd(a + 3, v.w);
}

// ---------------------------------------------------------------------------
// GEMM + bias: out[32-row tile][128] = agg @ W + b.
// Block = 256 threads; thread owns (col = tid&127, 16 rows). Inner loop:
// 1 LDG of W[k][col] (coalesced, W stays L1-resident) broadcast-multiplied
// against 16 smem row values (same address across the warp -> broadcast,
// conflict-free). 2048 FFMA per thread vs 128 LDG -> FFMA-bound.
// ---------------------------------------------------------------------------
__global__ void __launch_bounds__(256) gemm_kernel(const float* __restrict__ W,
                                                   const float* __restrict__ bias,
                                                   float* __restrict__ out) {
    __shared__ float sA[32][D];
    const int row0 = blockIdx.x * 32;
    const int tid = threadIdx.x;

    const int nrows = (N_NODES - row0) < 32 ? (N_NODES - row0) : 32;
    const float4* srcA = (const float4*)(g_agg + (size_t)row0 * D);
    float4* dA = (float4*)sA;
    const int n4 = nrows * (D / 4);
    for (int i = tid; i < n4; i += 256) dA[i] = srcA[i];
    __syncthreads();

    const int col = tid & 127;
    const int rbase = (tid >> 7) * 16;  // 0 or 16

    float acc[16];
#pragma unroll
    for (int r = 0; r < 16; r++) acc[r] = 0.f;

#pragma unroll 4
    for (int k = 0; k < D; k++) {
        float wk = W[k * D + col];
#pragma unroll
        for (int r = 0; r < 16; r++) acc[r] += sA[rbase + r][k] * wk;
    }

    const float bv = bias[col];
#pragma unroll
    for (int r = 0; r < 16; r++) {
        int row = row0 + rbase + r;
        if (row < N_NODES) out[(size_t)row * D + col] = acc[r] + bv;
    }
}

// ---------------------------------------------------------------------------
// Launch: detect -> zero -> edge aggregate -> gemm (sequential, same stream).
// Graph-capturable: kernel launches only, no sync, no alloc.
// ---------------------------------------------------------------------------
extern "C" void kernel_launch(void* const* d_in, const int* in_sizes, int n_in,
                              void* d_out, int out_size) {
    const float* feat = (const float*)d_in[0];  // [50000, 128] f32
    const void*  src  = d_in[1];                // [640000] int32 or int64
    const void*  dst  = d_in[2];                // [640000] int32 or int64
    const float* W    = (const float*)d_in[3];  // [128, 128] f32
    const float* b    = (const float*)d_in[4];  // [1, 128] f32
    float* out = (float*)d_out;                 // [50000, 128] f32

    detect_kernel<<<1, 32>>>(src, dst);
    zero_kernel<<<1024, 256>>>();
    // one warp per edge: 640000 warps, 8 warps/block -> 80000 blocks
    edge_kernel<<<(N_EDGES * 32 + 255) / 256, 256>>>(feat, src, dst);
    gemm_kernel<<<(N_NODES + 31) / 32, 256>>>(W, b, out);
}

// round 2
// speedup vs baseline: 1.5997x; 1.5997x over previous
#include <cuda_runtime.h>
#include <cuda_bf16.h>

#define N_NODES 50000
#define D 128
#define N_EDGES 640000
#define SCAN_THREADS 1024

// ---- device scratch (no allocs allowed) ----
__device__ float g_Y[(size_t)N_NODES * D];   // feat @ W   (25.6 MB)
__device__ int   g_count[N_NODES];           // degree histogram
__device__ int   g_cursor[N_NODES];          // scatter cursors
__device__ int   g_offset[N_NODES];          // exclusive prefix of counts
__device__ int   g_src_sorted[N_EDGES];      // src index grouped by dst
__device__ int   g_is64;                     // 1 if edge indices are int64

// ---------------------------------------------------------------------------
// Detect int64 vs int32 edge indices. If data is int32, an int64 read packs
// two indices; the high half is a random node index (nonzero w.p. ~1-2e-5),
// so any out-of-range value among 128 checks identifies int32.
// ---------------------------------------------------------------------------
__global__ void detect_kernel(const void* __restrict__ srcp,
                              const void* __restrict__ dstp) {
    if (threadIdx.x == 0 && blockIdx.x == 0) {
        const long long* s64 = (const long long*)srcp;
        const long long* d64 = (const long long*)dstp;
        int ok = 1;
        for (int i = 0; i < 64; i++) {
            long long a = s64[i];
            long long b = d64[i];
            if (a < 0 || a >= N_NODES || b < 0 || b >= N_NODES) { ok = 0; break; }
        }
        g_is64 = ok;
    }
}

__device__ __forceinline__ int load_idx(const void* __restrict__ p, int i) {
    return g_is64 ? (int)((const long long*)p)[i] : ((const int*)p)[i];
}

// ---------------------------------------------------------------------------
// Zero the integer scratch (counts + cursors) each call.
// ---------------------------------------------------------------------------
__global__ void zero_ints_kernel() {
    int i = blockIdx.x * blockDim.x + threadIdx.x;
    if (i < N_NODES) { g_count[i] = 0; g_cursor[i] = 0; }
}

// ---------------------------------------------------------------------------
// Degree histogram over dst.
// ---------------------------------------------------------------------------
__global__ void hist_kernel(const void* __restrict__ dstp) {
    int e = blockIdx.x * blockDim.x + threadIdx.x;
    if (e < N_EDGES) atomicAdd(&g_count[load_idx(dstp, e)], 1);
}

// ---------------------------------------------------------------------------
// Single-block exclusive scan of g_count -> g_offset (N=50000).
// Each thread sums a 49-element chunk; Hillis-Steele scan of 1024 partials.
// ---------------------------------------------------------------------------
__global__ void __launch_bounds__(SCAN_THREADS) scan_kernel() {
    __shared__ int ssum[SCAN_THREADS];
    const int t = threadIdx.x;
    const int C = (N_NODES + SCAN_THREADS - 1) / SCAN_THREADS;  // 49
    const int lo = t * C;
    const int hi = (lo + C < N_NODES) ? lo + C : N_NODES;

    int s = 0;
    for (int i = lo; i < hi; i++) s += g_count[i];
    ssum[t] = s;
    __syncthreads();

    for (int off = 1; off < SCAN_THREADS; off <<= 1) {
        int v = ssum[t];
        int u = (t >= off) ? ssum[t - off] : 0;
        __syncthreads();
        ssum[t] = v + u;
        __syncthreads();
    }

    int run = (t == 0) ? 0 : ssum[t - 1];
    for (int i = lo; i < hi; i++) { g_offset[i] = run; run += g_count[i]; }
}

// ---------------------------------------------------------------------------
// Scatter src indices into dst-grouped order (counting sort, int atomics).
// ---------------------------------------------------------------------------
__global__ void scatter_kernel(const void* __restrict__ srcp,
                               const void* __restrict__ dstp) {
    int e = blockIdx.x * blockDim.x + threadIdx.x;
    if (e >= N_EDGES) return;
    int d = load_idx(dstp, e);
    int s = load_idx(srcp, e);
    int pos = atomicAdd(&g_cursor[d], 1);
    g_src_sorted[g_offset[d] + pos] = s;
}

// ---------------------------------------------------------------------------
// GEMM: g_Y = feat @ W. Tile = 32 rows x 128 cols, 256 threads.
// Thread owns (col = tid&127, 16 rows). k-step 4: 16x LDS.128 (uniform
// broadcast, conflict-free) + 4x LDG.32 (W L1-resident) per 64 FFMA.
// ---------------------------------------------------------------------------
__global__ void __launch_bounds__(256) gemm_kernel(const float* __restrict__ feat,
                                                   const float* __restrict__ W) {
    __shared__ float sA[32][D];
    const int row0 = blockIdx.x * 32;
    const int tid = threadIdx.x;

    const int nrows = (N_NODES - row0) < 32 ? (N_NODES - row0) : 32;
    const float4* srcA = (const float4*)(feat + (size_t)row0 * D);
    float4* dA = (float4*)sA;
    const int n4 = nrows * (D / 4);
    for (int i = tid; i < n4; i += 256) dA[i] = srcA[i];
    __syncthreads();

    const int col = tid & 127;
    const int rbase = (tid >> 7) * 16;  // 0 or 16

    float acc[16];
#pragma unroll
    for (int r = 0; r < 16; r++) acc[r] = 0.f;

#pragma unroll
    for (int k = 0; k < D; k += 4) {
        float w0 = W[(k + 0) * D + col];
        float w1 = W[(k + 1) * D + col];
        float w2 = W[(k + 2) * D + col];
        float w3 = W[(k + 3) * D + col];
#pragma unroll
        for (int r = 0; r < 16; r++) {
            float4 a = *(const float4*)&sA[rbase + r][k];
            acc[r] += a.x * w0 + a.y * w1 + a.z * w2 + a.w * w3;
        }
    }

#pragma unroll
    for (int r = 0; r < 16; r++) {
        int row = row0 + rbase + r;
        if (row < N_NODES) g_Y[(size_t)row * D + col] = acc[r];
    }
}

// ---------------------------------------------------------------------------
// Aggregation: out[n] = sum_{e in seg(n)} Y[src_sorted[e]] + b.
// One warp per node; lane handles 16B (float4) of the 128-float row.
// No float atomics; Y is fully L2-resident so this is an L2-read pass.
// ---------------------------------------------------------------------------
__global__ void __launch_bounds__(256) agg_kernel(const float* __restrict__ bias,
                                                  float* __restrict__ out) {
    int warp = (blockIdx.x * blockDim.x + threadIdx.x) >> 5;
    int lane = threadIdx.x & 31;
    if (warp >= N_NODES) return;

    const int beg = g_offset[warp];
    const int end = beg + g_count[warp];

    float4 acc = make_float4(0.f, 0.f, 0.f, 0.f);
#pragma unroll 4
    for (int e = beg; e < end; e++) {
        int s = g_src_sorted[e];  // uniform across warp -> one sector
        float4 v = ((const float4*)(g_Y + (size_t)s * D))[lane];
        acc.x += v.x; acc.y += v.y; acc.z += v.z; acc.w += v.w;
    }

    float4 bv = ((const float4*)bias)[lane];
    float4 o = make_float4(acc.x + bv.x, acc.y + bv.y, acc.z + bv.z, acc.w + bv.w);
    ((float4*)(out + (size_t)warp * D))[lane] = o;
}

// ---------------------------------------------------------------------------
// Launch. Graph-capturable: kernels only, no sync, no alloc.
// ---------------------------------------------------------------------------
extern "C" void kernel_launch(void* const* d_in, const int* in_sizes, int n_in,
                              void* d_out, int out_size) {
    const float* feat = (const float*)d_in[0];  // [50000, 128] f32
    const void*  src  = d_in[1];                // [640000] int32/int64
    const void*  dst  = d_in[2];                // [640000] int32/int64
    const float* W    = (const float*)d_in[3];  // [128, 128] f32
    const float* b    = (const float*)d_in[4];  // [1, 128] f32
    float* out = (float*)d_out;                 // [50000, 128] f32

    detect_kernel<<<1, 32>>>(src, dst);
    zero_ints_kernel<<<(N_NODES + 255) / 256, 256>>>();
    hist_kernel<<<(N_EDGES + 255) / 256, 256>>>(dst);
    scan_kernel<<<1, SCAN_THREADS>>>();
    scatter_kernel<<<(N_EDGES + 255) / 256, 256>>>(src, dst);
    gemm_kernel<<<(N_NODES + 31) / 32, 256>>>(feat, W);
    agg_kernel<<<(N_NODES * 32 + 255) / 256, 256>>>(b, out);
}

// round 3
// speedup vs baseline: 2.2464x; 1.4043x over previous
#include <cuda_runtime.h>
#include <cuda_bf16.h>

#define N_NODES 50000
#define D 128
#define N_EDGES 640000
#define SCAN_B 256
#define NBLK ((N_NODES + SCAN_B - 1) / SCAN_B)   // 196

// ---- device scratch (no allocs allowed) ----
__device__ float g_Y[(size_t)N_NODES * D];   // feat @ W   (25.6 MB)
__device__ int   g_count[N_NODES];           // degree histogram
__device__ int   g_offset[N_NODES];          // per-block-local exclusive prefix (mutated by scatter)
__device__ int   g_bsum[NBLK];               // per-block totals
__device__ int   g_bbase[SCAN_B];            // exclusive scan of block totals
__device__ int   g_src_sorted[N_EDGES];      // src index grouped by dst
__device__ int   g_is64;                     // 1 if edge indices are int64

// ---------------------------------------------------------------------------
// init: block 0 detects index dtype (parallel warp ballot); other blocks zero
// the histogram. If data is int32, an int64 read packs two indices and the
// high half is a random node index (nonzero w.p. ~1-2e-5), so any
// out-of-range value among 128 checks identifies int32.
// ---------------------------------------------------------------------------
__global__ void init_kernel(const void* __restrict__ srcp,
                            const void* __restrict__ dstp) {
    if (blockIdx.x == 0) {
        if (threadIdx.x < 32) {
            const long long* s64 = (const long long*)srcp;
            const long long* d64 = (const long long*)dstp;
            int lane = threadIdx.x;
            int bad = 0;
#pragma unroll
            for (int r = 0; r < 2; r++) {
                int i = lane + r * 32;
                long long a = s64[i];
                long long b = d64[i];
                bad |= (a < 0 || a >= N_NODES || b < 0 || b >= N_NODES);
            }
            unsigned m = __ballot_sync(0xFFFFFFFFu, bad);
            if (lane == 0) g_is64 = (m == 0u);
        }
    } else {
        int i = (blockIdx.x - 1) * blockDim.x + threadIdx.x;
        if (i < N_NODES) g_count[i] = 0;
    }
}

__device__ __forceinline__ int load_idx(const void* __restrict__ p, int i) {
    return g_is64 ? (int)((const long long*)p)[i] : ((const int*)p)[i];
}

// ---------------------------------------------------------------------------
// Degree histogram over dst (L2 int atomics, spread addresses).
// ---------------------------------------------------------------------------
__global__ void hist_kernel(const void* __restrict__ dstp) {
    int e = blockIdx.x * blockDim.x + threadIdx.x;
    if (e < N_EDGES) atomicAdd(&g_count[load_idx(dstp, e)], 1);
}

// ---------------------------------------------------------------------------
// Scan phase 1: per-block inclusive scan of counts.
// g_offset[i] = exclusive prefix WITHIN the block; g_bsum[b] = block total.
// ---------------------------------------------------------------------------
__global__ void __launch_bounds__(SCAN_B) scan1_kernel() {
    __shared__ int s[SCAN_B];
    const int t = threadIdx.x;
    const int i = blockIdx.x * SCAN_B + t;
    int c = (i < N_NODES) ? g_count[i] : 0;
    s[t] = c;
    __syncthreads();
#pragma unroll
    for (int off = 1; off < SCAN_B; off <<= 1) {
        int v = s[t];
        int u = (t >= off) ? s[t - off] : 0;
        __syncthreads();
        s[t] = v + u;
        __syncthreads();
    }
    if (i < N_NODES) g_offset[i] = s[t] - c;       // local exclusive
    if (t == SCAN_B - 1) g_bsum[blockIdx.x] = s[t];
}

// ---------------------------------------------------------------------------
// Scan phase 2: one block scans the 196 block totals -> exclusive bases.
// ---------------------------------------------------------------------------
__global__ void __launch_bounds__(SCAN_B) scan2_kernel() {
    __shared__ int s[SCAN_B];
    const int t = threadIdx.x;
    int v0 = (t < NBLK) ? g_bsum[t] : 0;
    s[t] = v0;
    __syncthreads();
#pragma unroll
    for (int off = 1; off < SCAN_B; off <<= 1) {
        int v = s[t];
        int u = (t >= off) ? s[t - off] : 0;
        __syncthreads();
        s[t] = v + u;
        __syncthreads();
    }
    g_bbase[t] = s[t] - v0;                         // exclusive base per block
}

// ---------------------------------------------------------------------------
// Scatter src indices into dst-grouped order. Uses g_offset as the live
// cursor (atomicAdd), adds the block base to form the global position.
// After this kernel, g_offset[n] = local exclusive END of segment n.
// ---------------------------------------------------------------------------
__global__ void scatter_kernel(const void* __restrict__ srcp,
                               const void* __restrict__ dstp) {
    int e = blockIdx.x * blockDim.x + threadIdx.x;
    if (e >= N_EDGES) return;
    int d = load_idx(dstp, e);
    int s = load_idx(srcp, e);
    int pos = atomicAdd(&g_offset[d], 1) + g_bbase[d >> 8];
    g_src_sorted[pos] = s;
}

// ---------------------------------------------------------------------------
// GEMM: g_Y = feat @ W. Tile = 32 rows x 128 cols, 256 threads.
// Thread owns (col = tid&127, 16 rows). k-step 4: LDS.128 uniform broadcast
// (conflict-free) + 4x LDG.32 (W L1-resident) per 64 FFMA.
// ---------------------------------------------------------------------------
__global__ void __launch_bounds__(256) gemm_kernel(const float* __restrict__ feat,
                                                   const float* __restrict__ W) {
    __shared__ float sA[32][D];
    const int row0 = blockIdx.x * 32;
    const int tid = threadIdx.x;

    const int nrows = (N_NODES - row0) < 32 ? (N_NODES - row0) : 32;
    const float4* srcA = (const float4*)(feat + (size_t)row0 * D);
    float4* dA = (float4*)sA;
    const int n4 = nrows * (D / 4);
    for (int i = tid; i < n4; i += 256) dA[i] = srcA[i];
    __syncthreads();

    const int col = tid & 127;
    const int rbase = (tid >> 7) * 16;  // 0 or 16

    float acc[16];
#pragma unroll
    for (int r = 0; r < 16; r++) acc[r] = 0.f;

#pragma unroll
    for (int k = 0; k < D; k += 4) {
        float w0 = W[(k + 0) * D + col];
        float w1 = W[(k + 1) * D + col];
        float w2 = W[(k + 2) * D + col];
        float w3 = W[(k + 3) * D + col];
#pragma unroll
        for (int r = 0; r < 16; r++) {
            float4 a = *(const float4*)&sA[rbase + r][k];
            acc[r] += a.x * w0 + a.y * w1 + a.z * w2 + a.w * w3;
        }
    }

#pragma unroll
    for (int r = 0; r < 16; r++) {
        int row = row0 + rbase + r;
        if (row < N_NODES) g_Y[(size_t)row * D + col] = acc[r];
    }
}

// ---------------------------------------------------------------------------
// Aggregation: out[n] = sum_{e in seg(n)} Y[src_sorted[e]] + b.
// One warp per node; lane handles a float4 slice of the 128-float row.
// Segment bounds reconstructed: end_local = g_offset[n] (post-scatter),
// beg_global = end_local - count + bbase.
// ---------------------------------------------------------------------------
__global__ void __launch_bounds__(256) agg_kernel(const float* __restrict__ bias,
                                                  float* __restrict__ out) {
    int node = (blockIdx.x * blockDim.x + threadIdx.x) >> 5;
    int lane = threadIdx.x & 31;
    if (node >= N_NODES) return;

    const int cnt = g_count[node];
    const int beg = g_offset[node] - cnt + g_bbase[node >> 8];
    const int end = beg + cnt;

    float4 acc = make_float4(0.f, 0.f, 0.f, 0.f);
#pragma unroll 4
    for (int e = beg; e < end; e++) {
        int s = g_src_sorted[e];  // uniform across warp
        float4 v = ((const float4*)(g_Y + (size_t)s * D))[lane];
        acc.x += v.x; acc.y += v.y; acc.z += v.z; acc.w += v.w;
    }

    float4 bv = ((const float4*)bias)[lane];
    float4 o = make_float4(acc.x + bv.x, acc.y + bv.y, acc.z + bv.z, acc.w + bv.w);
    ((float4*)(out + (size_t)node * D))[lane] = o;
}

// ---------------------------------------------------------------------------
// Launch. Graph-capturable: kernels only, no sync, no alloc.
// ---------------------------------------------------------------------------
extern "C" void kernel_launch(void* const* d_in, const int* in_sizes, int n_in,
                              void* d_out, int out_size) {
    const float* feat = (const float*)d_in[0];  // [50000, 128] f32
    const void*  src  = d_in[1];                // [640000] int32/int64
    const void*  dst  = d_in[2];                // [640000] int32/int64
    const float* W    = (const float*)d_in[3];  // [128, 128] f32
    const float* b    = (const float*)d_in[4];  // [1, 128] f32
    float* out = (float*)d_out;                 // [50000, 128] f32

    init_kernel<<<1 + (N_NODES + 255) / 256, 256>>>(src, dst);
    hist_kernel<<<(N_EDGES + 255) / 256, 256>>>(dst);
    scan1_kernel<<<NBLK, SCAN_B>>>();
    scan2_kernel<<<1, SCAN_B>>>();
    scatter_kernel<<<(N_EDGES + 255) / 256, 256>>>(src, dst);
    gemm_kernel<<<(N_NODES + 31) / 32, 256>>>(feat, W);
    agg_kernel<<<(N_NODES * 32 + 255) / 256, 256>>>(b, out);
}

// round 4
// speedup vs baseline: 2.6460x; 1.1779x over previous
#include <cuda_runtime.h>
#include <cuda_bf16.h>

#define N_NODES 50000
#define D 128
#define N_EDGES 640000
#define SCAN_B 256
#define NBLK ((N_NODES + SCAN_B - 1) / SCAN_B)   // 196
#define NGB ((N_NODES + 127) / 128)              // 391 gemm blocks
#define NHB 128                                  // hist blocks

// ---- device scratch (no allocs allowed) ----
__device__ float g_Y[(size_t)N_NODES * D];   // feat @ W   (25.6 MB)
__device__ int   g_count[N_NODES];           // degree histogram
__device__ int   g_offset[N_NODES];          // block-local exclusive prefix (mutated by scatter)
__device__ int   g_bsum[NBLK];               // per-block totals
__device__ int   g_bbase[SCAN_B];            // exclusive scan of block totals
__device__ int   g_src_sorted[N_EDGES];      // src index grouped by dst
__device__ int   g_is64;                     // 1 if edge indices are int64
__device__ unsigned g_scan_tickets;          // zero-init; reset by last scan block

// ---------------------------------------------------------------------------
// init: block 0 detects index dtype (warp ballot over 128 probes); other
// blocks zero the histogram. int32 data read as int64 packs two indices whose
// high half is a random node index (nonzero w.p. ~1-2e-5) -> out-of-range.
// ---------------------------------------------------------------------------
__global__ void init_kernel(const void* __restrict__ srcp,
                            const void* __restrict__ dstp) {
    if (blockIdx.x == 0) {
        if (threadIdx.x < 32) {
            const long long* s64 = (const long long*)srcp;
            const long long* d64 = (const long long*)dstp;
            int lane = threadIdx.x;
            int bad = 0;
#pragma unroll
            for (int r = 0; r < 2; r++) {
                int i = lane + r * 32;
                long long a = s64[i];
                long long b = d64[i];
                bad |= (a < 0 || a >= N_NODES || b < 0 || b >= N_NODES);
            }
            unsigned m = __ballot_sync(0xFFFFFFFFu, bad);
            if (lane == 0) g_is64 = (m == 0u);
        }
    } else {
        int i = (blockIdx.x - 1) * blockDim.x + threadIdx.x;
        if (i < N_NODES) g_count[i] = 0;
    }
}

__device__ __forceinline__ int load_idx(const void* __restrict__ p, int i) {
    return g_is64 ? (int)((const long long*)p)[i] : ((const int*)p)[i];
}

// ---------------------------------------------------------------------------
// FUSED: gemm (blocks [0, NGB)) + dst histogram (blocks [NGB, NGB+NHB)).
// The L2-atomic hist hides under the fma-bound gemm wave.
//
// gemm: g_Y = feat @ W. Tile 128x128, 256 threads, 8x8 per-thread register
// tile, Kc=32 staged in smem. sA padded to stride 33 -> conflict-free STS.32
// staging (bank = r + 4*kq, bijective) and 2-address broadcast LDS reads.
// Per k: 8 LDS.32 + 2 LDS.128 + 64 FFMA (86% fma issue share).
// ---------------------------------------------------------------------------
__global__ void __launch_bounds__(256) histgemm_kernel(const float* __restrict__ feat,
                                                       const float* __restrict__ W,
                                                       const void* __restrict__ dstp) {
    if (blockIdx.x >= NGB) {
        // ---- histogram part ----
        int e = (blockIdx.x - NGB) * 256 + threadIdx.x;
        const int stride = NHB * 256;
        for (; e < N_EDGES; e += stride)
            atomicAdd(&g_count[load_idx(dstp, e)], 1);
        return;
    }

    // ---- gemm part ----
    __shared__ float sA[128 * 33];   // [row][k], stride 33
    __shared__ float sB[32 * 128];   // [k][col]

    const int row0 = blockIdx.x * 128;
    const int tid = threadIdx.x;
    const int tx = tid & 15;         // col group: cols tx*8 .. tx*8+8
    const int ty = tid >> 4;         // row group: rows ty*8 .. ty*8+8

    float acc[8][8];
#pragma unroll
    for (int i = 0; i < 8; i++)
#pragma unroll
        for (int j = 0; j < 8; j++) acc[i][j] = 0.f;

    const int kq = tid & 7;          // A-stage: f4 index within k-chunk
    const int ar0 = tid >> 3;        // A-stage: row 0..31
    const int c4 = tid & 31;         // B-stage: f4 col 0..31
    const int kr0 = tid >> 5;        // B-stage: k row 0..7

    for (int k0 = 0; k0 < D; k0 += 32) {
        // stage A: 128 rows x 32 k (guarded for last block)
#pragma unroll
        for (int p = 0; p < 4; p++) {
            int r = ar0 + p * 32;
            int row = row0 + r;
            float4 v = make_float4(0.f, 0.f, 0.f, 0.f);
            if (row < N_NODES)
                v = *(const float4*)(feat + (size_t)row * D + k0 + kq * 4);
            float* dst = &sA[r * 33 + kq * 4];
            dst[0] = v.x; dst[1] = v.y; dst[2] = v.z; dst[3] = v.w;
        }
        // stage B: 32 k x 128 cols
#pragma unroll
        for (int p = 0; p < 4; p++) {
            int kr = kr0 + p * 8;
            *(float4*)(sB + kr * 128 + c4 * 4) =
                *(const float4*)(W + (size_t)(k0 + kr) * D + c4 * 4);
        }
        __syncthreads();

#pragma unroll 8
        for (int k = 0; k < 32; k++) {
            float a[8];
#pragma unroll
            for (int i = 0; i < 8; i++) a[i] = sA[(ty * 8 + i) * 33 + k];
            float4 b0 = *(const float4*)(sB + k * 128 + tx * 8);
            float4 b1 = *(const float4*)(sB + k * 128 + tx * 8 + 4);
            float b[8] = {b0.x, b0.y, b0.z, b0.w, b1.x, b1.y, b1.z, b1.w};
#pragma unroll
            for (int i = 0; i < 8; i++)
#pragma unroll
                for (int j = 0; j < 8; j++) acc[i][j] += a[i] * b[j];
        }
        __syncthreads();
    }

#pragma unroll
    for (int i = 0; i < 8; i++) {
        int row = row0 + ty * 8 + i;
        if (row < N_NODES) {
            float* orow = g_Y + (size_t)row * D + tx * 8;
            *(float4*)(orow)     = make_float4(acc[i][0], acc[i][1], acc[i][2], acc[i][3]);
            *(float4*)(orow + 4) = make_float4(acc[i][4], acc[i][5], acc[i][6], acc[i][7]);
        }
    }
}

// ---------------------------------------------------------------------------
// Scan (fused 2-phase): per-block inclusive scan of counts; the LAST block to
// finish (atomic ticket) scans the 196 block totals into g_bbase, then resets
// the ticket so graph replays are deterministic.
// ---------------------------------------------------------------------------
__global__ void __launch_bounds__(SCAN_B) scan_kernel() {
    __shared__ int s[SCAN_B];
    __shared__ int lastflag;
    const int t = threadIdx.x;
    const int i = blockIdx.x * SCAN_B + t;

    int c = (i < N_NODES) ? g_count[i] : 0;
    s[t] = c;
    __syncthreads();
#pragma unroll
    for (int off = 1; off < SCAN_B; off <<= 1) {
        int v = s[t];
        int u = (t >= off) ? s[t - off] : 0;
        __syncthreads();
        s[t] = v + u;
        __syncthreads();
    }
    if (i < N_NODES) g_offset[i] = s[t] - c;       // local exclusive
    if (t == SCAN_B - 1) g_bsum[blockIdx.x] = s[t];

    __threadfence();
    if (t == 0) {
        unsigned tk = atomicAdd(&g_scan_tickets, 1u);
        lastflag = (tk == NBLK - 1);
    }
    __syncthreads();

    if (lastflag) {
        int v0 = (t < NBLK) ? g_bsum[t] : 0;
        s[t] = v0;
        __syncthreads();
#pragma unroll
        for (int off = 1; off < SCAN_B; off <<= 1) {
            int v = s[t];
            int u = (t >= off) ? s[t - off] : 0;
            __syncthreads();
            s[t] = v + u;
            __syncthreads();
        }
        g_bbase[t] = s[t] - v0;
        if (t == 0) g_scan_tickets = 0;            // reset for next replay
    }
}

// ---------------------------------------------------------------------------
// Scatter src indices into dst-grouped order. g_offset is the live cursor;
// block base added on the fly. Post: g_offset[n] = local exclusive END.
// ---------------------------------------------------------------------------
__global__ void scatter_kernel(const void* __restrict__ srcp,
                               const void* __restrict__ dstp) {
    int e = blockIdx.x * blockDim.x + threadIdx.x;
    if (e >= N_EDGES) return;
    int d = load_idx(dstp, e);
    int s = load_idx(srcp, e);
    int pos = atomicAdd(&g_offset[d], 1) + g_bbase[d >> 8];
    g_src_sorted[pos] = s;
}

// ---------------------------------------------------------------------------
// Aggregation: out[n] = sum_{e in seg(n)} Y[src_sorted[e]] + b.
// One warp per node, lane = float4 slice. L2-read-bound (Y resident).
// ---------------------------------------------------------------------------
__global__ void __launch_bounds__(256) agg_kernel(const float* __restrict__ bias,
                                                  float* __restrict__ out) {
    int node = (blockIdx.x * blockDim.x + threadIdx.x) >> 5;
    int lane = threadIdx.x & 31;
    if (node >= N_NODES) return;

    const int cnt = g_count[node];
    const int beg = g_offset[node] - cnt + g_bbase[node >> 8];
    const int end = beg + cnt;

    float4 acc = make_float4(0.f, 0.f, 0.f, 0.f);
#pragma unroll 4
    for (int e = beg; e < end; e++) {
        int s = g_src_sorted[e];  // uniform across warp
        float4 v = ((const float4*)(g_Y + (size_t)s * D))[lane];
        acc.x += v.x; acc.y += v.y; acc.z += v.z; acc.w += v.w;
    }

    float4 bv = ((const float4*)bias)[lane];
    ((float4*)(out + (size_t)node * D))[lane] =
        make_float4(acc.x + bv.x, acc.y + bv.y, acc.z + bv.z, acc.w + bv.w);
}

// ---------------------------------------------------------------------------
// Launch: 5 kernels, graph-capturable (no sync, no alloc).
// ---------------------------------------------------------------------------
extern "C" void kernel_launch(void* const* d_in, const int* in_sizes, int n_in,
                              void* d_out, int out_size) {
    const float* feat = (const float*)d_in[0];  // [50000, 128] f32
    const void*  src  = d_in[1];                // [640000] int32/int64
    const void*  dst  = d_in[2];                // [640000] int32/int64
    const float* W    = (const float*)d_in[3];  // [128, 128] f32
    const float* b    = (const float*)d_in[4];  // [1, 128] f32
    float* out = (float*)d_out;                 // [50000, 128] f32

    init_kernel<<<1 + (N_NODES + 255) / 256, 256>>>(src, dst);
    histgemm_kernel<<<NGB + NHB, 256>>>(feat, W, dst);
    scan_kernel<<<NBLK, SCAN_B>>>();
    scatter_kernel<<<(N_EDGES + 255) / 256, 256>>>(src, dst);
    agg_kernel<<<(N_NODES * 32 + 255) / 256, 256>>>(b, out);
}

// round 5
// speedup vs baseline: 2.9161x; 1.1021x over previous
#include <cuda_runtime.h>
#include <cuda_bf16.h>

#define N_NODES 50000
#define D 128
#define N_EDGES 640000
#define S_BLK 64                       // sort blocks (must be < 148: wave-1 resident)
#define G_BLK 232                      // gemm blocks
#define GRID_TOT (S_BLK + G_BLK)       // 296 = 2/SM * 148
#define NGB ((N_NODES + 127) / 128)    // 391 gemm tiles
#define CHUNK 4                        // scan items per sort thread (64*256*4 = 65536 >= 50000)

// ---- device scratch (no allocs allowed; zero-initialized) ----
__device__ float g_Y[(size_t)N_NODES * D];   // feat @ W   (25.6 MB)
__device__ int   g_count[N_NODES];           // degree histogram
__device__ int   g_offset[N_NODES];          // global exclusive prefix; scatter mutates to end
__device__ int   g_bsum[S_BLK];              // per-sort-block totals
__device__ int   g_bbase[S_BLK];             // exclusive scan of block totals
__device__ int   g_src_sorted[N_EDGES];      // src index grouped by dst
__device__ int   g_is64;                     // 1 if edge indices are int64
__device__ unsigned g_bar_cnt;               // sort barrier arrivals (self-resetting)
__device__ unsigned g_bar_done;              // end-of-kernel reset ticket

// Global spin barrier among the S_BLK sort blocks. target = phase * S_BLK.
__device__ __forceinline__ void sort_barrier(unsigned target) {
    __syncthreads();
    if (threadIdx.x == 0) {
        __threadfence();
        atomicAdd(&g_bar_cnt, 1u);
        while (*((volatile unsigned*)&g_bar_cnt) < target) __nanosleep(64);
        __threadfence();
    }
    __syncthreads();
}

// ---------------------------------------------------------------------------
// Mega kernel.
//  blocks [0, S_BLK):       zero+detect -> hist -> scan -> scatter
//  blocks [S_BLK, GRID_TOT): g_Y = feat @ W  (128x128 tiles, 8x8 reg tile)
// ---------------------------------------------------------------------------
__global__ void __launch_bounds__(256, 2)
mega_kernel(const float* __restrict__ feat, const float* __restrict__ W,
            const void* __restrict__ srcp, const void* __restrict__ dstp) {
    __shared__ float sA[128 * 33];   // gemm A tile, stride-33 padded
    __shared__ float sB[32 * 128];   // gemm B tile
    __shared__ int   ss[256];        // sort: block scan workspace

    const int tid = threadIdx.x;

    if (blockIdx.x < S_BLK) {
        // ================= SORT CHAIN =================
        const int b = blockIdx.x;
        const int st = b * 256 + tid;          // sort-thread id, 0..16383
        const int NT = S_BLK * 256;            // 16384

        // ---- P0: zero histogram + detect index dtype ----
        for (int i = st; i < N_NODES; i += NT) g_count[i] = 0;
        if (b == 0 && tid < 32) {
            // int32 data read as int64 packs two indices; high half is a
            // random node index (nonzero w.p. ~1-2e-5) -> out-of-range check.
            const long long* s64 = (const long long*)srcp;
            const long long* d64 = (const long long*)dstp;
            int bad = 0;
#pragma unroll
            for (int r = 0; r < 2; r++) {
                int i = tid + r * 32;
                long long a = s64[i], c = d64[i];
                bad |= (a < 0 || a >= N_NODES || c < 0 || c >= N_NODES);
            }
            unsigned m = __ballot_sync(0xFFFFFFFFu, bad);
            if (tid == 0) g_is64 = (m == 0u);
        }
        sort_barrier(1u * S_BLK);

        // ---- P1: histogram over dst ----
        const int is64 = g_is64;
        if (is64) {
            const long long* dd = (const long long*)dstp;
            for (int e = st; e < N_EDGES; e += NT)
                atomicAdd(&g_count[(int)dd[e]], 1);
        } else {
            const int* dd = (const int*)dstp;
            for (int e = st; e < N_EDGES; e += NT)
                atomicAdd(&g_count[dd[e]], 1);
        }
        sort_barrier(2u * S_BLK);

        // ---- P2a: thread sums + block scan ----
        const int g0 = st * CHUNK;
        int csum = 0;
        int cv[CHUNK];
#pragma unroll
        for (int i = 0; i < CHUNK; i++) {
            int g = g0 + i;
            cv[i] = (g < N_NODES) ? g_count[g] : 0;
            csum += cv[i];
        }
        ss[tid] = csum;
        __syncthreads();
#pragma unroll
        for (int off = 1; off < 256; off <<= 1) {
            int v = ss[tid];
            int u = (tid >= off) ? ss[tid - off] : 0;
            __syncthreads();
            ss[tid] = v + u;
            __syncthreads();
        }
        const int texcl = ss[tid] - csum;
        if (tid == 255) g_bsum[b] = ss[255];
        sort_barrier(3u * S_BLK);

        // ---- P2b: block 0 scans the 64 block totals ----
        if (b == 0) {
            int v0 = (tid < S_BLK) ? g_bsum[tid] : 0;
            ss[tid] = v0;
            __syncthreads();
#pragma unroll
            for (int off = 1; off < S_BLK; off <<= 1) {
                int v = ss[tid];
                int u = (tid >= off) ? ss[tid - off] : 0;
                __syncthreads();
                ss[tid] = v + u;
                __syncthreads();
            }
            if (tid < S_BLK) g_bbase[tid] = ss[tid] - v0;
        }
        sort_barrier(4u * S_BLK);

        // ---- P2c: write global exclusive offsets ----
        {
            int run = g_bbase[b] + texcl;
#pragma unroll
            for (int i = 0; i < CHUNK; i++) {
                int g = g0 + i;
                if (g < N_NODES) g_offset[g] = run;
                run += cv[i];
            }
        }
        sort_barrier(5u * S_BLK);

        // ---- P3: scatter src into dst-grouped order ----
        if (is64) {
            const long long* dd = (const long long*)dstp;
            const long long* sv = (const long long*)srcp;
            for (int e = st; e < N_EDGES; e += NT) {
                int d = (int)dd[e];
                int s = (int)sv[e];
                g_src_sorted[atomicAdd(&g_offset[d], 1)] = s;
            }
        } else {
            const int* dd = (const int*)dstp;
            const int* sv = (const int*)srcp;
            for (int e = st; e < N_EDGES; e += NT) {
                int d = dd[e];
                int s = sv[e];
                g_src_sorted[atomicAdd(&g_offset[d], 1)] = s;
            }
        }

        // ---- reset barrier counters for next graph replay ----
        __syncthreads();
        if (tid == 0) {
            __threadfence();
            unsigned old = atomicAdd(&g_bar_done, 1u);
            if (old == S_BLK - 1) { g_bar_cnt = 0; g_bar_done = 0; }
        }
        return;
    }

    // ================= GEMM: g_Y = feat @ W =================
    const int tx = tid & 15;          // col group (8 cols)
    const int ty = tid >> 4;          // row group (8 rows)
    const int kq = tid & 7;           // A stage: f4 index in k-chunk
    const int ar0 = tid >> 3;         // A stage: row 0..31
    const int c4 = tid & 31;          // B stage: f4 col
    const int kr0 = tid >> 5;         // B stage: k row 0..7

    for (int tile = blockIdx.x - S_BLK; tile < NGB; tile += G_BLK) {
        const int row0 = tile * 128;

        float acc[8][8];
#pragma unroll
        for (int i = 0; i < 8; i++)
#pragma unroll
            for (int j = 0; j < 8; j++) acc[i][j] = 0.f;

        for (int k0 = 0; k0 < D; k0 += 32) {
#pragma unroll
            for (int p = 0; p < 4; p++) {
                int r = ar0 + p * 32;
                int row = row0 + r;
                float4 v = make_float4(0.f, 0.f, 0.f, 0.f);
                if (row < N_NODES)
                    v = *(const float4*)(feat + (size_t)row * D + k0 + kq * 4);
                float* dst = &sA[r * 33 + kq * 4];
                dst[0] = v.x; dst[1] = v.y; dst[2] = v.z; dst[3] = v.w;
            }
#pragma unroll
            for (int p = 0; p < 4; p++) {
                int kr = kr0 + p * 8;
                *(float4*)(sB + kr * 128 + c4 * 4) =
                    *(const float4*)(W + (size_t)(k0 + kr) * D + c4 * 4);
            }
            __syncthreads();

#pragma unroll 8
            for (int k = 0; k < 32; k++) {
                float a[8];
#pragma unroll
                for (int i = 0; i < 8; i++) a[i] = sA[(ty * 8 + i) * 33 + k];
                float4 b0 = *(const float4*)(sB + k * 128 + tx * 8);
                float4 b1 = *(const float4*)(sB + k * 128 + tx * 8 + 4);
                float bb[8] = {b0.x, b0.y, b0.z, b0.w, b1.x, b1.y, b1.z, b1.w};
#pragma unroll
                for (int i = 0; i < 8; i++)
#pragma unroll
                    for (int j = 0; j < 8; j++) acc[i][j] += a[i] * bb[j];
            }
            __syncthreads();
        }

#pragma unroll
        for (int i = 0; i < 8; i++) {
            int row = row0 + ty * 8 + i;
            if (row < N_NODES) {
                float* orow = g_Y + (size_t)row * D + tx * 8;
                *(float4*)(orow)     = make_float4(acc[i][0], acc[i][1], acc[i][2], acc[i][3]);
                *(float4*)(orow + 4) = make_float4(acc[i][4], acc[i][5], acc[i][6], acc[i][7]);
            }
        }
    }
}

// ---------------------------------------------------------------------------
// Aggregation: out[n] = sum_{e in seg(n)} Y[src_sorted[e]] + b.
// One warp per node, lane = float4 slice. L2-read-bound (Y resident).
// Post-scatter g_offset[n] = global segment END; beg = end - count.
// ---------------------------------------------------------------------------
__global__ void __launch_bounds__(256) agg_kernel(const float* __restrict__ bias,
                                                  float* __restrict__ out) {
    int node = (blockIdx.x * blockDim.x + threadIdx.x) >> 5;
    int lane = threadIdx.x & 31;
    if (node >= N_NODES) return;

    const int end = g_offset[node];
    const int beg = end - g_count[node];

    float4 acc = make_float4(0.f, 0.f, 0.f, 0.f);
#pragma unroll 4
    for (int e = beg; e < end; e++) {
        int s = g_src_sorted[e];  // uniform across warp
        float4 v = ((const float4*)(g_Y + (size_t)s * D))[lane];
        acc.x += v.x; acc.y += v.y; acc.z += v.z; acc.w += v.w;
    }

    float4 bv = ((const float4*)bias)[lane];
    ((float4*)(out + (size_t)node * D))[lane] =
        make_float4(acc.x + bv.x, acc.y + bv.y, acc.z + bv.z, acc.w + bv.w);
}

// ---------------------------------------------------------------------------
// Launch: 2 kernels, graph-capturable (no sync, no alloc).
// ---------------------------------------------------------------------------
extern "C" void kernel_launch(void* const* d_in, const int* in_sizes, int n_in,
                              void* d_out, int out_size) {
    const float* feat = (const float*)d_in[0];  // [50000, 128] f32
    const void*  src  = d_in[1];                // [640000] int32/int64
    const void*  dst  = d_in[2];                // [640000] int32/int64
    const float* W    = (const float*)d_in[3];  // [128, 128] f32
    const float* b    = (const float*)d_in[4];  // [1, 128] f32
    float* out = (float*)d_out;                 // [50000, 128] f32

    mega_kernel<<<GRID_TOT, 256>>>(feat, W, src, dst);
    agg_kernel<<<(N_NODES * 32 + 255) / 256, 256>>>(b, out);
}